// round 12
// baseline (speedup 1.0000x reference)
#include <cuda_runtime.h>
#include <math.h>

#define BB 128
#define TT 512
#define DD 128
#define HH 384
#define GG 1542
#define GPAD 1664
#define HSS 64
#define CK 10
#define GT 24
#define NBLK (GT * 4)
#define KH 384
#define APAD 40

__device__ float g_h[(size_t)TT * BB * HH];
__device__ float g_dist[TT * BB];
__device__ float g_theme[(size_t)TT * BB * HH];
__device__ float g_wct[CK * HH * HH];
__device__ float g_xk[(size_t)TT * BB * GPAD];
__device__ unsigned g_cnt2[4];
__device__ volatile unsigned g_gen2[4];

typedef unsigned long long u64;
__device__ __forceinline__ u64 pk2(float a, float b) {
    u64 r; asm("mov.b64 %0,{%1,%2};" : "=l"(r) : "f"(a), "f"(b)); return r;
}
__device__ __forceinline__ void fma2(u64 &d, u64 a, u64 b) {
    asm("fma.rn.f32x2 %0,%1,%2,%0;" : "+l"(d) : "l"(a), "l"(b));
}
__device__ __forceinline__ float2 up2(u64 v) {
    float2 r; asm("mov.b64 {%0,%1},%2;" : "=f"(r.x), "=f"(r.y) : "l"(v)); return r;
}
__device__ __forceinline__ float ftanh(float x) {
    float y; asm("tanh.approx.f32 %0,%1;" : "=f"(y) : "f"(x)); return y;
}
__device__ __forceinline__ float sgm(float x) { return 0.5f * ftanh(0.5f * x) + 0.5f; }

__device__ __forceinline__ void group_bar(int grp) {
    __syncthreads();
    if (threadIdx.x == 0) {
        unsigned old = g_gen2[grp];
        __threadfence();
        if (atomicAdd(&g_cnt2[grp], 1u) == GT - 1) {
            g_cnt2[grp] = 0;
            __threadfence();
            g_gen2[grp] = old + 1;
        } else {
            while (g_gen2[grp] == old) { }
            __threadfence();
        }
    }
    __syncthreads();
}

__device__ __forceinline__ void calc_dis(int t, int b, float *dis) {
    float cs = 0.f, c[CK];
    #pragma unroll
    for (int k = 0; k < CK; k++) {
        int s = t - (CK - 1) + k;
        cs += (s >= 0) ? g_dist[s * BB + b] : 0.f;
        c[k] = cs;
    }
    float mx = c[0];
    #pragma unroll
    for (int k = 1; k < CK; k++) mx = fmaxf(mx, c[k]);
    float sum = 0.f;
    #pragma unroll
    for (int k = 0; k < CK; k++) { c[k] = __expf(c[k] - mx); sum += c[k]; }
    float is = 1.f / sum;
    #pragma unroll
    for (int k = 0; k < CK; k++) dis[k] = c[k] * is;
}

__global__ void wct_kernel(const float * __restrict__ Wc) {
    int e = blockIdx.x * 256 + threadIdx.x;
    if (e < CK * HH * HH) {
        int o = e % HH, i = (e / HH) % HH, k = e / (HH * HH);
        g_wct[e] = Wc[((size_t)o * HH + i) * CK + k];
    }
}

// ---------- XK precompute ----------
#define XK_FFMA(COMP)                                                       \
    {                                                                       \
        ulonglong2 b0v = *(const ulonglong2 *)&Bs[kk][tx * 4];              \
        ulonglong2 b1v = *(const ulonglong2 *)&Bs[kk][tx * 4 + 64];         \
        _Pragma("unroll")                                                   \
        for (int rr = 0; rr < 8; rr++) {                                    \
            float av = a4[rr].COMP;                                         \
            u64 aa = pk2(av, av);                                           \
            fma2(acc[rr][0], aa, b0v.x); fma2(acc[rr][1], aa, b0v.y);       \
            fma2(acc[rr][2], aa, b1v.x); fma2(acc[rr][3], aa, b1v.y);       \
        }                                                                   \
        kk++;                                                               \
    }

__global__ __launch_bounds__(256) void xk_kernel(
    const float * __restrict__ x, const float * __restrict__ Wk,
    const float * __restrict__ bk, const float * __restrict__ Wr,
    const float * __restrict__ br)
{
    int b = blockIdx.x >> 2, t0 = (blockIdx.x & 3) * 128;
    int g0 = blockIdx.y * 128;
    int tid = threadIdx.x, tx = tid & 15, ty = tid >> 4;
    __shared__ __align__(16) float As[128][20];
    __shared__ __align__(16) float Bs[16][128];

    u64 acc[8][4];
    #pragma unroll
    for (int a = 0; a < 8; a++)
        #pragma unroll
        for (int c = 0; c < 4; c++) acc[a][c] = 0ull;

    for (int ch = 0; ch < 8; ch++) {
        int k0 = ch * 16;
        __syncthreads();
        #pragma unroll
        for (int l = 0; l < 8; l++) {
            int e = tid + l * 256;
            As[e >> 4][e & 15] = x[((size_t)b * TT + t0 + (e >> 4)) * DD + k0 + (e & 15)];
            int g = g0 + (e & 127);
            Bs[e >> 7][e & 127] = (g < GG) ? Wk[(size_t)(k0 + (e >> 7)) * GG + g] : 0.f;
        }
        __syncthreads();
        #pragma unroll
        for (int kq = 0; kq < 4; kq++) {
            float4 a4[8];
            #pragma unroll
            for (int rr = 0; rr < 8; rr++)
                a4[rr] = *(const float4 *)&As[ty * 8 + rr][kq * 4];
            int kk = kq * 4;
            XK_FFMA(x) XK_FFMA(y) XK_FFMA(z) XK_FFMA(w)
        }
    }
    #pragma unroll
    for (int rr = 0; rr < 8; rr++) {
        int t = t0 + ty * 8 + rr;
        #pragma unroll
        for (int c = 0; c < 4; c++) {
            float2 v = up2(acc[rr][c]);
            #pragma unroll
            for (int l = 0; l < 2; l++) {
                int g = g0 + (c >> 1) * 64 + tx * 4 + (c & 1) * 2 + l;
                if (g < GG) {
                    float bias = bk[g] + br[g] + Wk[(size_t)DD * GG + g] + Wr[(size_t)HH * GG + g];
                    int gp = (g < 6) ? (1536 + g) : (g - 6);
                    g_xk[((size_t)t * BB + b) * GPAD + gp] = (l ? v.y : v.x) + bias;
                }
            }
        }
    }
}

// ---------- Persistent phase-1 (unchanged, proven) ----------
__global__ __launch_bounds__(512, 1) void phase1_main(const float * __restrict__ Wr)
{
    extern __shared__ float sm[];
    float *Bs   = sm;
    float *Bsm  = Bs + KH * 64;
    float *As   = Bsm + KH * 8;
    float *Msum = As + KH * APAD;
    float *fms  = Msum + 4 * 192;
    float *ims  = fms + 96;

    int tid = threadIdx.x, blk = blockIdx.x;
    int gt = blk % GT, bt = blk / GT;
    int b0 = bt * 32;

    for (int j = 0; j < (KH * 64) / 512; j++) {
        int e = tid + j * 512;
        int gg = e & 63, k = e >> 6, q = gg >> 4, m = gg & 15;
        Bs[e] = Wr[(size_t)k * GG + 6 + 384 * q + 16 * gt + m];
    }
    for (int e = tid; e < KH * 8; e += 512) {
        int g = e & 7, k = e >> 3;
        Bsm[e] = (g < 6) ? Wr[(size_t)k * GG + g] : 0.f;
    }
    __syncthreads();

    int kc = tid >> 7, r = tid & 127;
    int tx = r & 15, ty = r >> 4;
    int sb = tid >> 4, sj = tid & 15;
    int ub = tid >> 4, um = tid & 15;
    int ui = gt * 16 + um, ul = ui >> 7;
    float creg = 0.f;
    int mid0 = 2 * r, mb = mid0 / 6, mg0 = mid0 % 6;

    for (int t = 0; t < TT; t++) {
        float4 xkp[4];
        if (kc == 0) {
            int gp = 384 * (tx >> 2) + 16 * gt + (tx & 3) * 4;
            #pragma unroll
            for (int a = 0; a < 4; a++)
                xkp[a] = *(const float4 *)&g_xk[((size_t)t * BB + b0 + ty * 4 + a) * GPAD + gp];
        }
        float xkm[6];
        if (tid >= 128 && tid < 160) {
            int b = tid - 128;
            float4 v4 = *(const float4 *)&g_xk[((size_t)t * BB + b0 + b) * GPAD + 1536];
            float2 v2 = *(const float2 *)&g_xk[((size_t)t * BB + b0 + b) * GPAD + 1540];
            xkm[0] = v4.x; xkm[1] = v4.y; xkm[2] = v4.z; xkm[3] = v4.w;
            xkm[4] = v2.x; xkm[5] = v2.y;
        }

        #pragma unroll
        for (int j = 0; j < 6; j++) {
            int k4 = (sj + j * 16) * 4;
            float4 v;
            if (t > 0) v = *(const float4 *)&g_h[((size_t)(t - 1) * BB + b0 + sb) * HH + k4];
            else { v.x = v.y = v.z = v.w = 0.f; }
            As[(k4 + 0) * APAD + sb] = v.x;
            As[(k4 + 1) * APAD + sb] = v.y;
            As[(k4 + 2) * APAD + sb] = v.z;
            As[(k4 + 3) * APAD + sb] = v.w;
        }
        __syncthreads();

        u64 acc[4][2];
        #pragma unroll
        for (int a = 0; a < 4; a++) { acc[a][0] = 0ull; acc[a][1] = 0ull; }
        int kbeg = kc * (KH / 4);
        #pragma unroll 6
        for (int kk = kbeg; kk < kbeg + KH / 4; kk++) {
            float4 av = *(const float4 *)&As[kk * APAD + ty * 4];
            ulonglong2 bv = *(const ulonglong2 *)&Bs[kk * 64 + tx * 4];
            u64 aa;
            aa = pk2(av.x, av.x); fma2(acc[0][0], aa, bv.x); fma2(acc[0][1], aa, bv.y);
            aa = pk2(av.y, av.y); fma2(acc[1][0], aa, bv.x); fma2(acc[1][1], aa, bv.y);
            aa = pk2(av.z, av.z); fma2(acc[2][0], aa, bv.x); fma2(acc[2][1], aa, bv.y);
            aa = pk2(av.w, av.w); fma2(acc[3][0], aa, bv.x); fma2(acc[3][1], aa, bv.y);
        }
        float mp0 = 0.f, mp1 = 0.f;
        if (r < 96) {
            for (int kk = kbeg; kk < kbeg + KH / 4; kk++) {
                float a = As[kk * APAD + mb];
                mp0 += a * Bsm[kk * 8 + mg0];
                mp1 += a * Bsm[kk * 8 + mg0 + 1];
            }
        }
        __syncthreads();

        ulonglong2 *red = (ulonglong2 *)As;
        float *res = (float *)(red + 3 * 512);
        if (kc) {
            #pragma unroll
            for (int a = 0; a < 4; a++) {
                ulonglong2 v; v.x = acc[a][0]; v.y = acc[a][1];
                red[(size_t)(kc - 1) * 512 + a * 128 + r] = v;
            }
        }
        if (r < 96) *(float2 *)&Msum[kc * 192 + mid0] = make_float2(mp0, mp1);
        __syncthreads();

        if (kc == 0) {
            #pragma unroll
            for (int a = 0; a < 4; a++) {
                float2 s0 = up2(acc[a][0]), s1 = up2(acc[a][1]);
                #pragma unroll
                for (int q = 0; q < 3; q++) {
                    ulonglong2 v = red[(size_t)q * 512 + a * 128 + r];
                    float2 o0 = up2(v.x), o1 = up2(v.y);
                    s0.x += o0.x; s0.y += o0.y; s1.x += o1.x; s1.y += o1.y;
                }
                float4 w;
                w.x = s0.x + xkp[a].x; w.y = s0.y + xkp[a].y;
                w.z = s1.x + xkp[a].z; w.w = s1.y + xkp[a].w;
                *(float4 *)&res[(ty * 4 + a) * 64 + tx * 4] = w;
            }
        }
        if (tid >= 128 && tid < 160) {
            int b = tid - 128;
            float pre[6];
            #pragma unroll
            for (int g = 0; g < 6; g++)
                pre[g] = Msum[b * 6 + g] + Msum[192 + b * 6 + g]
                       + Msum[384 + b * 6 + g] + Msum[576 + b * 6 + g] + xkm[g];
            float m = fmaxf(pre[0], fmaxf(pre[1], pre[2]));
            float e0 = __expf(pre[0] - m), e1 = __expf(pre[1] - m), e2 = __expf(pre[2] - m);
            float inv = 1.f / (e0 + e1 + e2);
            float f0 = e0 * inv, f1 = f0 + e1 * inv, f2 = f1 + e2 * inv;
            fms[b * 3 + 0] = f0; fms[b * 3 + 1] = f1; fms[b * 3 + 2] = f2;
            float mi = fmaxf(pre[3], fmaxf(pre[4], pre[5]));
            float q0 = __expf(pre[3] - mi), q1 = __expf(pre[4] - mi), q2 = __expf(pre[5] - mi);
            float iv = 1.f / (q0 + q1 + q2);
            float i2 = q2 * iv, i1 = i2 + q1 * iv, i0 = i1 + q0 * iv;
            ims[b * 3 + 0] = i0; ims[b * 3 + 1] = i1; ims[b * 3 + 2] = i2;
            if (gt == 0) g_dist[t * BB + b0 + b] = 1.f - (f0 + f1 + f2) * (1.f / 3.f);
        }
        __syncthreads();

        {
            float fgv = sgm(res[ub * 64 + um]);
            float igv = sgm(res[ub * 64 + 16 + um]);
            float ogv = sgm(res[ub * 64 + 32 + um]);
            float civ = ftanh(res[ub * 64 + 48 + um]);
            float fm = fms[ub * 3 + ul], im = ims[ub * 3 + ul];
            float ov = fm * im;
            creg = creg * (ov * fgv + fm - ov) + civ * (ov * igv + im - ov);
            g_h[((size_t)t * BB + b0 + ub) * HH + ui] = ogv * ftanh(creg);
        }
        group_bar(bt);
    }
}

// ---------- theme: 16 b/block (Ws/Wrs reuse doubled) ----------
__global__ __launch_bounds__(256) void theme_kernel(
    const float * __restrict__ Ws, const float * __restrict__ bs,
    const float * __restrict__ Wrs, const float * __restrict__ brs)
{
    int t = blockIdx.x, b0 = blockIdx.y * 16, tid = threadIdx.x;
    __shared__ float dis_s[16][CK], wm[16][HH], s1[16][HSS];
    if (tid < 16) calc_dis(t, b0 + tid, dis_s[tid]);
    __syncthreads();
    #pragma unroll
    for (int j = 0; j < 24; j++) {
        int e = tid + j * 256, b = e / HH, i = e % HH;
        float a = 0.f;
        #pragma unroll
        for (int k = 0; k < CK; k++) {
            int s = t - (CK - 1) + k;
            if (s >= 0) a += dis_s[b][k] * g_h[((size_t)s * BB + b0 + b) * HH + i];
        }
        wm[b][i] = a * (1.f / CK);
    }
    __syncthreads();
    #pragma unroll
    for (int j = 0; j < 4; j++) {
        int e = tid + j * 256, b = e / HSS, hs = e % HSS;
        float a = 0.f;
        for (int i = 0; i < HH; i++) a += wm[b][i] * Ws[i * HSS + hs];
        s1[b][hs] = fmaxf(a + bs[hs], 0.f);
    }
    __syncthreads();
    #pragma unroll
    for (int j = 0; j < 24; j++) {
        int e = tid + j * 256, b = e / HH, o = e % HH;
        float a = 0.f;
        #pragma unroll
        for (int hs = 0; hs < HSS; hs++) a += s1[b][hs] * Wrs[hs * HH + o];
        g_theme[((size_t)t * BB + b0 + b) * HH + o] = sgm(a + brs[o]);
    }
}

// ---------- conv: 512 threads, micro 8b x 4o, 4 warps/SMSP ----------
#define CONV_FFMA(COMP)                                                     \
    {                                                                       \
        ulonglong2 bv = *(const ulonglong2 *)&Bs[kk][tx * 4];               \
        _Pragma("unroll")                                                   \
        for (int rr = 0; rr < 8; rr++) {                                    \
            float av = a4[rr].COMP;                                         \
            u64 aa = pk2(av, av);                                           \
            fma2(acc[rr][0], aa, bv.x); fma2(acc[rr][1], aa, bv.y);         \
        }                                                                   \
        kk++;                                                               \
    }

__global__ __launch_bounds__(512) void conv_kernel(const float * __restrict__ bc,
                                                   float * __restrict__ out)
{
    int t = blockIdx.x, o0 = blockIdx.y * 128, tid = threadIdx.x;
    int tx = tid & 31, ty = tid >> 5;           // tx: o-quad (32), ty: b-octet (16)
    __shared__ float dis_s[BB][CK];
    __shared__ __align__(16) float As[BB][36];
    __shared__ __align__(16) float Bs[32][128];
    if (tid < BB) calc_dis(t, tid, dis_s[tid]);
    __syncthreads();

    u64 acc[8][2];
    #pragma unroll
    for (int a = 0; a < 8; a++) { acc[a][0] = 0ull; acc[a][1] = 0ull; }

    const int NCH = CK * (HH / 32);   // 120
    float4 pa[2], pb[2];
    {
        int s = t - (CK - 1);
        #pragma unroll
        for (int l = 0; l < 2; l++) {
            int f = tid + l * 512;
            int ab = f >> 3, ai = (f & 7) * 4;
            pa[l].x = pa[l].y = pa[l].z = pa[l].w = 0.f;
            if (s >= 0) pa[l] = *(const float4 *)&g_h[((size_t)s * BB + ab) * HH + ai];
            int br_ = f >> 5, bo = (f & 31) * 4;
            pb[l] = *(const float4 *)&g_wct[(size_t)br_ * HH + o0 + bo];
        }
    }
    for (int ch = 0; ch < NCH; ch++) {
        int k = ch / 12;
        __syncthreads();
        #pragma unroll
        for (int l = 0; l < 2; l++) {
            int f = tid + l * 512;
            int ab = f >> 3, ai = (f & 7) * 4;
            float d = dis_s[ab][k];
            float4 v = pa[l];
            v.x *= d; v.y *= d; v.z *= d; v.w *= d;
            *(float4 *)&As[ab][ai] = v;
            int br_ = f >> 5, bo = (f & 31) * 4;
            *(float4 *)&Bs[br_][bo] = pb[l];
        }
        __syncthreads();
        if (ch + 1 < NCH) {
            int k2 = (ch + 1) / 12, i0 = ((ch + 1) % 12) * 32, s = t - (CK - 1) + k2;
            #pragma unroll
            for (int l = 0; l < 2; l++) {
                int f = tid + l * 512;
                int ab = f >> 3, ai = (f & 7) * 4;
                pa[l].x = pa[l].y = pa[l].z = pa[l].w = 0.f;
                if (s >= 0) pa[l] = *(const float4 *)&g_h[((size_t)s * BB + ab) * HH + i0 + ai];
                int br_ = f >> 5, bo = (f & 31) * 4;
                pb[l] = *(const float4 *)&g_wct[((size_t)k2 * HH + i0 + br_) * HH + o0 + bo];
            }
        }
        #pragma unroll
        for (int kq = 0; kq < 8; kq++) {
            float4 a4[8];
            #pragma unroll
            for (int rr = 0; rr < 8; rr++)
                a4[rr] = *(const float4 *)&As[ty * 8 + rr][kq * 4];
            int kk = kq * 4;
            CONV_FFMA(x) CONV_FFMA(y) CONV_FFMA(z) CONV_FFMA(w)
        }
    }
    float4 bc4 = *(const float4 *)&bc[o0 + tx * 4];
    #pragma unroll
    for (int rr = 0; rr < 8; rr++) {
        int b = ty * 8 + rr;
        float2 v0 = up2(acc[rr][0]), v1 = up2(acc[rr][1]);
        float4 th = *(const float4 *)&g_theme[((size_t)t * BB + b) * HH + o0 + tx * 4];
        float4 hh = *(const float4 *)&g_h[((size_t)t * BB + b) * HH + o0 + tx * 4];
        float4 w;
        w.x = th.x * (v0.x + bc4.x) + hh.x;
        w.y = th.y * (v0.y + bc4.y) + hh.y;
        w.z = th.z * (v1.x + bc4.z) + hh.z;
        w.w = th.w * (v1.y + bc4.w) + hh.w;
        *(float4 *)&out[((size_t)b * TT + t) * HH + o0 + tx * 4] = w;
    }
}

extern "C" void kernel_launch(void* const* d_in, const int* in_sizes, int n_in,
                              void* d_out, int out_size) {
    const float *x   = (const float *)d_in[0];
    const float *Wk  = (const float *)d_in[2];
    const float *bk  = (const float *)d_in[3];
    const float *Wr  = (const float *)d_in[4];
    const float *br  = (const float *)d_in[5];
    const float *Ws  = (const float *)d_in[6];
    const float *bs  = (const float *)d_in[7];
    const float *Wrs = (const float *)d_in[8];
    const float *brs = (const float *)d_in[9];
    const float *Wc  = (const float *)d_in[10];
    const float *bc  = (const float *)d_in[11];
    float *out = (float *)d_out;

    const int smem_floats = KH * 64 + KH * 8 + KH * APAD + 4 * 192 + 96 + 96;
    const int smem_bytes = smem_floats * 4;
    cudaFuncSetAttribute(phase1_main,
                         cudaFuncAttributeMaxDynamicSharedMemorySize, smem_bytes);

    xk_kernel<<<dim3(512, 13), 256>>>(x, Wk, bk, Wr, br);
    wct_kernel<<<(CK * HH * HH + 255) / 256, 256>>>(Wc);
    phase1_main<<<NBLK, 512, smem_bytes>>>(Wr);
    theme_kernel<<<dim3(TT, 8), 256>>>(Ws, bs, Wrs, brs);
    conv_kernel<<<dim3(TT, 3), 512>>>(bc, out);
}

// round 13
// speedup vs baseline: 1.0428x; 1.0428x over previous
#include <cuda_runtime.h>
#include <math.h>

#define BB 128
#define TT 512
#define DD 128
#define HH 384
#define GG 1542
#define GPAD 1664
#define HSS 64
#define CK 10
#define GT 24
#define NBLK (GT * 4)
#define KH 384
#define APAD 40

__device__ float g_h[(size_t)TT * BB * HH];
__device__ float g_dist[TT * BB];
__device__ float g_theme[(size_t)TT * BB * HH];
__device__ float g_wct[CK * HH * HH];
__device__ float g_xk[(size_t)TT * BB * GPAD];
__device__ unsigned g_cnt2[4];
__device__ unsigned g_gen2[4];

typedef unsigned long long u64;
__device__ __forceinline__ u64 pk2(float a, float b) {
    u64 r; asm("mov.b64 %0,{%1,%2};" : "=l"(r) : "f"(a), "f"(b)); return r;
}
__device__ __forceinline__ void fma2(u64 &d, u64 a, u64 b) {
    asm("fma.rn.f32x2 %0,%1,%2,%0;" : "+l"(d) : "l"(a), "l"(b));
}
__device__ __forceinline__ float2 up2(u64 v) {
    float2 r; asm("mov.b64 {%0,%1},%2;" : "=f"(r.x), "=f"(r.y) : "l"(v)); return r;
}
__device__ __forceinline__ float ftanh(float x) {
    float y; asm("tanh.approx.f32 %0,%1;" : "=f"(y) : "f"(x)); return y;
}
__device__ __forceinline__ float sgm(float x) { return 0.5f * ftanh(0.5f * x) + 0.5f; }

__device__ __forceinline__ void group_bar(int grp) {
    __syncthreads();
    if (threadIdx.x == 0) {
        unsigned *gp = &g_gen2[grp];
        unsigned old;
        asm volatile("ld.global.u32 %0, [%1];" : "=r"(old) : "l"(gp) : "memory");
        unsigned prev;
        asm volatile("atom.add.acq_rel.gpu.global.u32 %0, [%1], 1;"
                     : "=r"(prev) : "l"(&g_cnt2[grp]) : "memory");
        if (prev == GT - 1) {
            g_cnt2[grp] = 0;
            asm volatile("st.release.gpu.global.u32 [%0], %1;"
                         :: "l"(gp), "r"(old + 1) : "memory");
        } else {
            unsigned v;
            do {
                asm volatile("ld.acquire.gpu.global.u32 %0, [%1];"
                             : "=r"(v) : "l"(gp) : "memory");
            } while (v == old);
        }
    }
    __syncthreads();
}

__device__ __forceinline__ void calc_dis(int t, int b, float *dis) {
    float cs = 0.f, c[CK];
    #pragma unroll
    for (int k = 0; k < CK; k++) {
        int s = t - (CK - 1) + k;
        cs += (s >= 0) ? g_dist[s * BB + b] : 0.f;
        c[k] = cs;
    }
    float mx = c[0];
    #pragma unroll
    for (int k = 1; k < CK; k++) mx = fmaxf(mx, c[k]);
    float sum = 0.f;
    #pragma unroll
    for (int k = 0; k < CK; k++) { c[k] = __expf(c[k] - mx); sum += c[k]; }
    float is = 1.f / sum;
    #pragma unroll
    for (int k = 0; k < CK; k++) dis[k] = c[k] * is;
}

__global__ void wct_kernel(const float * __restrict__ Wc) {
    int e = blockIdx.x * 256 + threadIdx.x;
    if (e < CK * HH * HH) {
        int o = e % HH, i = (e / HH) % HH, k = e / (HH * HH);
        g_wct[e] = Wc[((size_t)o * HH + i) * CK + k];
    }
}

// ---------- XK precompute ----------
#define XK_FFMA(COMP)                                                       \
    {                                                                       \
        ulonglong2 b0v = *(const ulonglong2 *)&Bs[kk][tx * 4];              \
        ulonglong2 b1v = *(const ulonglong2 *)&Bs[kk][tx * 4 + 64];         \
        _Pragma("unroll")                                                   \
        for (int rr = 0; rr < 8; rr++) {                                    \
            float av = a4[rr].COMP;                                         \
            u64 aa = pk2(av, av);                                           \
            fma2(acc[rr][0], aa, b0v.x); fma2(acc[rr][1], aa, b0v.y);       \
            fma2(acc[rr][2], aa, b1v.x); fma2(acc[rr][3], aa, b1v.y);       \
        }                                                                   \
        kk++;                                                               \
    }

__global__ __launch_bounds__(256) void xk_kernel(
    const float * __restrict__ x, const float * __restrict__ Wk,
    const float * __restrict__ bk, const float * __restrict__ Wr,
    const float * __restrict__ br)
{
    int b = blockIdx.x >> 2, t0 = (blockIdx.x & 3) * 128;
    int g0 = blockIdx.y * 128;
    int tid = threadIdx.x, tx = tid & 15, ty = tid >> 4;
    __shared__ __align__(16) float As[128][20];
    __shared__ __align__(16) float Bs[16][128];

    u64 acc[8][4];
    #pragma unroll
    for (int a = 0; a < 8; a++)
        #pragma unroll
        for (int c = 0; c < 4; c++) acc[a][c] = 0ull;

    for (int ch = 0; ch < 8; ch++) {
        int k0 = ch * 16;
        __syncthreads();
        #pragma unroll
        for (int l = 0; l < 8; l++) {
            int e = tid + l * 256;
            As[e >> 4][e & 15] = x[((size_t)b * TT + t0 + (e >> 4)) * DD + k0 + (e & 15)];
            int g = g0 + (e & 127);
            Bs[e >> 7][e & 127] = (g < GG) ? Wk[(size_t)(k0 + (e >> 7)) * GG + g] : 0.f;
        }
        __syncthreads();
        #pragma unroll
        for (int kq = 0; kq < 4; kq++) {
            float4 a4[8];
            #pragma unroll
            for (int rr = 0; rr < 8; rr++)
                a4[rr] = *(const float4 *)&As[ty * 8 + rr][kq * 4];
            int kk = kq * 4;
            XK_FFMA(x) XK_FFMA(y) XK_FFMA(z) XK_FFMA(w)
        }
    }
    #pragma unroll
    for (int rr = 0; rr < 8; rr++) {
        int t = t0 + ty * 8 + rr;
        #pragma unroll
        for (int c = 0; c < 4; c++) {
            float2 v = up2(acc[rr][c]);
            #pragma unroll
            for (int l = 0; l < 2; l++) {
                int g = g0 + (c >> 1) * 64 + tx * 4 + (c & 1) * 2 + l;
                if (g < GG) {
                    float bias = bk[g] + br[g] + Wk[(size_t)DD * GG + g] + Wr[(size_t)HH * GG + g];
                    int gp = (g < 6) ? (1536 + g) : (g - 6);
                    g_xk[((size_t)t * BB + b) * GPAD + gp] = (l ? v.y : v.x) + bias;
                }
            }
        }
    }
}

// ---------- Persistent phase-1 (R10 body, lighter barrier) ----------
__global__ __launch_bounds__(512, 1) void phase1_main(const float * __restrict__ Wr)
{
    extern __shared__ float sm[];
    float *Bs   = sm;
    float *Bsm  = Bs + KH * 64;
    float *As   = Bsm + KH * 8;
    float *Msum = As + KH * APAD;
    float *fms  = Msum + 4 * 192;
    float *ims  = fms + 96;

    int tid = threadIdx.x, blk = blockIdx.x;
    int gt = blk % GT, bt = blk / GT;
    int b0 = bt * 32;

    for (int j = 0; j < (KH * 64) / 512; j++) {
        int e = tid + j * 512;
        int gg = e & 63, k = e >> 6, q = gg >> 4, m = gg & 15;
        Bs[e] = Wr[(size_t)k * GG + 6 + 384 * q + 16 * gt + m];
    }
    for (int e = tid; e < KH * 8; e += 512) {
        int g = e & 7, k = e >> 3;
        Bsm[e] = (g < 6) ? Wr[(size_t)k * GG + g] : 0.f;
    }
    __syncthreads();

    int kc = tid >> 7, r = tid & 127;
    int tx = r & 15, ty = r >> 4;
    int sb = tid >> 4, sj = tid & 15;
    int ub = tid >> 4, um = tid & 15;
    int ui = gt * 16 + um, ul = ui >> 7;
    float creg = 0.f;
    int mid0 = 2 * r, mb = mid0 / 6, mg0 = mid0 % 6;

    for (int t = 0; t < TT; t++) {
        float4 xkp[4];
        if (kc == 0) {
            int gp = 384 * (tx >> 2) + 16 * gt + (tx & 3) * 4;
            #pragma unroll
            for (int a = 0; a < 4; a++)
                xkp[a] = *(const float4 *)&g_xk[((size_t)t * BB + b0 + ty * 4 + a) * GPAD + gp];
        }
        float xkm[6];
        if (tid >= 128 && tid < 160) {
            int b = tid - 128;
            float4 v4 = *(const float4 *)&g_xk[((size_t)t * BB + b0 + b) * GPAD + 1536];
            float2 v2 = *(const float2 *)&g_xk[((size_t)t * BB + b0 + b) * GPAD + 1540];
            xkm[0] = v4.x; xkm[1] = v4.y; xkm[2] = v4.z; xkm[3] = v4.w;
            xkm[4] = v2.x; xkm[5] = v2.y;
        }

        #pragma unroll
        for (int j = 0; j < 6; j++) {
            int k4 = (sj + j * 16) * 4;
            float4 v;
            if (t > 0) v = *(const float4 *)&g_h[((size_t)(t - 1) * BB + b0 + sb) * HH + k4];
            else { v.x = v.y = v.z = v.w = 0.f; }
            As[(k4 + 0) * APAD + sb] = v.x;
            As[(k4 + 1) * APAD + sb] = v.y;
            As[(k4 + 2) * APAD + sb] = v.z;
            As[(k4 + 3) * APAD + sb] = v.w;
        }
        __syncthreads();

        u64 acc[4][2];
        #pragma unroll
        for (int a = 0; a < 4; a++) { acc[a][0] = 0ull; acc[a][1] = 0ull; }
        int kbeg = kc * (KH / 4);
        #pragma unroll 6
        for (int kk = kbeg; kk < kbeg + KH / 4; kk++) {
            float4 av = *(const float4 *)&As[kk * APAD + ty * 4];
            ulonglong2 bv = *(const ulonglong2 *)&Bs[kk * 64 + tx * 4];
            u64 aa;
            aa = pk2(av.x, av.x); fma2(acc[0][0], aa, bv.x); fma2(acc[0][1], aa, bv.y);
            aa = pk2(av.y, av.y); fma2(acc[1][0], aa, bv.x); fma2(acc[1][1], aa, bv.y);
            aa = pk2(av.z, av.z); fma2(acc[2][0], aa, bv.x); fma2(acc[2][1], aa, bv.y);
            aa = pk2(av.w, av.w); fma2(acc[3][0], aa, bv.x); fma2(acc[3][1], aa, bv.y);
        }
        float mp0 = 0.f, mp1 = 0.f;
        if (r < 96) {
            for (int kk = kbeg; kk < kbeg + KH / 4; kk++) {
                float a = As[kk * APAD + mb];
                mp0 += a * Bsm[kk * 8 + mg0];
                mp1 += a * Bsm[kk * 8 + mg0 + 1];
            }
        }
        __syncthreads();

        ulonglong2 *red = (ulonglong2 *)As;
        float *res = (float *)(red + 3 * 512);
        if (kc) {
            #pragma unroll
            for (int a = 0; a < 4; a++) {
                ulonglong2 v; v.x = acc[a][0]; v.y = acc[a][1];
                red[(size_t)(kc - 1) * 512 + a * 128 + r] = v;
            }
        }
        if (r < 96) *(float2 *)&Msum[kc * 192 + mid0] = make_float2(mp0, mp1);
        __syncthreads();

        if (kc == 0) {
            #pragma unroll
            for (int a = 0; a < 4; a++) {
                float2 s0 = up2(acc[a][0]), s1 = up2(acc[a][1]);
                #pragma unroll
                for (int q = 0; q < 3; q++) {
                    ulonglong2 v = red[(size_t)q * 512 + a * 128 + r];
                    float2 o0 = up2(v.x), o1 = up2(v.y);
                    s0.x += o0.x; s0.y += o0.y; s1.x += o1.x; s1.y += o1.y;
                }
                float4 w;
                w.x = s0.x + xkp[a].x; w.y = s0.y + xkp[a].y;
                w.z = s1.x + xkp[a].z; w.w = s1.y + xkp[a].w;
                *(float4 *)&res[(ty * 4 + a) * 64 + tx * 4] = w;
            }
        }
        if (tid >= 128 && tid < 160) {
            int b = tid - 128;
            float pre[6];
            #pragma unroll
            for (int g = 0; g < 6; g++)
                pre[g] = Msum[b * 6 + g] + Msum[192 + b * 6 + g]
                       + Msum[384 + b * 6 + g] + Msum[576 + b * 6 + g] + xkm[g];
            float m = fmaxf(pre[0], fmaxf(pre[1], pre[2]));
            float e0 = __expf(pre[0] - m), e1 = __expf(pre[1] - m), e2 = __expf(pre[2] - m);
            float inv = 1.f / (e0 + e1 + e2);
            float f0 = e0 * inv, f1 = f0 + e1 * inv, f2 = f1 + e2 * inv;
            fms[b * 3 + 0] = f0; fms[b * 3 + 1] = f1; fms[b * 3 + 2] = f2;
            float mi = fmaxf(pre[3], fmaxf(pre[4], pre[5]));
            float q0 = __expf(pre[3] - mi), q1 = __expf(pre[4] - mi), q2 = __expf(pre[5] - mi);
            float iv = 1.f / (q0 + q1 + q2);
            float i2 = q2 * iv, i1 = i2 + q1 * iv, i0 = i1 + q0 * iv;
            ims[b * 3 + 0] = i0; ims[b * 3 + 1] = i1; ims[b * 3 + 2] = i2;
            if (gt == 0) g_dist[t * BB + b0 + b] = 1.f - (f0 + f1 + f2) * (1.f / 3.f);
        }
        __syncthreads();

        {
            float fgv = sgm(res[ub * 64 + um]);
            float igv = sgm(res[ub * 64 + 16 + um]);
            float ogv = sgm(res[ub * 64 + 32 + um]);
            float civ = ftanh(res[ub * 64 + 48 + um]);
            float fm = fms[ub * 3 + ul], im = ims[ub * 3 + ul];
            float ov = fm * im;
            creg = creg * (ov * fgv + fm - ov) + civ * (ov * igv + im - ov);
            g_h[((size_t)t * BB + b0 + ub) * HH + ui] = ogv * ftanh(creg);
        }
        group_bar(bt);
    }
}

// ---------- theme: persistent, Ws+Wrs resident in SMEM ----------
__global__ __launch_bounds__(256) void theme_kernel(
    const float * __restrict__ Ws, const float * __restrict__ bs,
    const float * __restrict__ Wrs, const float * __restrict__ brs)
{
    extern __shared__ __align__(16) float ts[];
    float *Wss  = ts;                    // [384][64]
    float *Wrss = Wss + 384 * 64;        // [64][384]
    float *wm   = Wrss + 64 * 384;       // [16][384]
    float *s1   = wm + 16 * 384;         // [16][64]
    float *diss = s1 + 16 * 64;          // [16][10]

    int tid = threadIdx.x;
    for (int e = tid; e < 6144; e += 256) ((float4 *)Wss)[e] = ((const float4 *)Ws)[e];
    for (int e = tid; e < 6144; e += 256) ((float4 *)Wrss)[e] = ((const float4 *)Wrs)[e];

    int b = tid >> 4, q = tid & 15;
    float4 bs4 = *(const float4 *)&bs[q * 4];

    for (int tile = blockIdx.x; tile < TT * 8; tile += gridDim.x) {
        int t = tile >> 3, b0 = (tile & 7) * 16;
        __syncthreads();
        if (tid < 16) calc_dis(t, b0 + tid, diss + tid * 10);
        __syncthreads();
        // wm = mean_k(dis * h)
        #pragma unroll
        for (int j = 0; j < 6; j++) {
            int i = (q + j * 16) * 4;
            float ax = 0.f, ay = 0.f, az = 0.f, aw = 0.f;
            #pragma unroll
            for (int k = 0; k < CK; k++) {
                int s = t - (CK - 1) + k;
                if (s >= 0) {
                    float d = diss[b * 10 + k];
                    float4 h4 = *(const float4 *)&g_h[((size_t)s * BB + b0 + b) * HH + i];
                    ax += d * h4.x; ay += d * h4.y; az += d * h4.z; aw += d * h4.w;
                }
            }
            float4 w; w.x = ax * .1f; w.y = ay * .1f; w.z = az * .1f; w.w = aw * .1f;
            *(float4 *)&wm[b * HH + i] = w;
        }
        __syncthreads();
        // s1 = relu(wm @ Ws + bs)
        {
            u64 a0 = 0ull, a1 = 0ull;
            #pragma unroll 8
            for (int i = 0; i < HH; i++) {
                float w = wm[b * HH + i];
                u64 ww = pk2(w, w);
                ulonglong2 W4 = *(const ulonglong2 *)&Wss[i * 64 + q * 4];
                fma2(a0, ww, W4.x); fma2(a1, ww, W4.y);
            }
            float2 v0 = up2(a0), v1 = up2(a1);
            float4 o;
            o.x = fmaxf(v0.x + bs4.x, 0.f); o.y = fmaxf(v0.y + bs4.y, 0.f);
            o.z = fmaxf(v1.x + bs4.z, 0.f); o.w = fmaxf(v1.y + bs4.w, 0.f);
            *(float4 *)&s1[b * 64 + q * 4] = o;
        }
        __syncthreads();
        // theme = sigmoid(s1 @ Wrs + brs)
        #pragma unroll
        for (int j = 0; j < 6; j++) {
            int o = (q + j * 16) * 4;
            u64 a0 = 0ull, a1 = 0ull;
            #pragma unroll 8
            for (int hs = 0; hs < HSS; hs++) {
                float sv = s1[b * 64 + hs];
                u64 ss = pk2(sv, sv);
                ulonglong2 W4 = *(const ulonglong2 *)&Wrss[hs * HH + o];
                fma2(a0, ss, W4.x); fma2(a1, ss, W4.y);
            }
            float4 br4 = *(const float4 *)&brs[o];
            float2 v0 = up2(a0), v1 = up2(a1);
            float4 w;
            w.x = sgm(v0.x + br4.x); w.y = sgm(v0.y + br4.y);
            w.z = sgm(v1.x + br4.z); w.w = sgm(v1.y + br4.w);
            *(float4 *)&g_theme[((size_t)t * BB + b0 + b) * HH + o] = w;
        }
    }
}

// ---------- conv (R10 proven version) ----------
#define CONV_FFMA(COMP)                                                     \
    {                                                                       \
        ulonglong2 b0v = *(const ulonglong2 *)&Bs[kk][tx * 4];              \
        ulonglong2 b1v = *(const ulonglong2 *)&Bs[kk][tx * 4 + 64];         \
        _Pragma("unroll")                                                   \
        for (int rr = 0; rr < 8; rr++) {                                    \
            float av = a4[rr].COMP;                                         \
            u64 aa = pk2(av, av);                                           \
            fma2(acc[rr][0], aa, b0v.x); fma2(acc[rr][1], aa, b0v.y);       \
            fma2(acc[rr][2], aa, b1v.x); fma2(acc[rr][3], aa, b1v.y);       \
        }                                                                   \
        kk++;                                                               \
    }

__global__ __launch_bounds__(256) void conv_kernel(const float * __restrict__ bc,
                                                   float * __restrict__ out)
{
    int t = blockIdx.x, o0 = blockIdx.y * 128, tid = threadIdx.x;
    int tx = tid & 15, ty = tid >> 4;
    __shared__ float dis_s[BB][CK];
    __shared__ __align__(16) float As[BB][36];
    __shared__ __align__(16) float Bs[32][128];
    if (tid < BB) calc_dis(t, tid, dis_s[tid]);
    __syncthreads();

    u64 acc[8][4];
    #pragma unroll
    for (int a = 0; a < 8; a++)
        #pragma unroll
        for (int c = 0; c < 4; c++) acc[a][c] = 0ull;

    const int NCH = CK * (HH / 32);
    float4 pa[4], pb[4];
    {
        int s = t - (CK - 1);
        #pragma unroll
        for (int l = 0; l < 4; l++) {
            int f = tid + l * 256;
            int ab = f >> 3, ai = (f & 7) * 4;
            pa[l].x = pa[l].y = pa[l].z = pa[l].w = 0.f;
            if (s >= 0) pa[l] = *(const float4 *)&g_h[((size_t)s * BB + ab) * HH + ai];
            int br_ = f >> 5, bo = (f & 31) * 4;
            pb[l] = *(const float4 *)&g_wct[(size_t)br_ * HH + o0 + bo];
        }
    }
    for (int ch = 0; ch < NCH; ch++) {
        int k = ch / 12;
        __syncthreads();
        #pragma unroll
        for (int l = 0; l < 4; l++) {
            int f = tid + l * 256;
            int ab = f >> 3, ai = (f & 7) * 4;
            float d = dis_s[ab][k];
            float4 v = pa[l];
            v.x *= d; v.y *= d; v.z *= d; v.w *= d;
            *(float4 *)&As[ab][ai] = v;
            int br_ = f >> 5, bo = (f & 31) * 4;
            *(float4 *)&Bs[br_][bo] = pb[l];
        }
        __syncthreads();
        if (ch + 1 < NCH) {
            int k2 = (ch + 1) / 12, i0 = ((ch + 1) % 12) * 32, s = t - (CK - 1) + k2;
            #pragma unroll
            for (int l = 0; l < 4; l++) {
                int f = tid + l * 256;
                int ab = f >> 3, ai = (f & 7) * 4;
                pa[l].x = pa[l].y = pa[l].z = pa[l].w = 0.f;
                if (s >= 0) pa[l] = *(const float4 *)&g_h[((size_t)s * BB + ab) * HH + i0 + ai];
                int br_ = f >> 5, bo = (f & 31) * 4;
                pb[l] = *(const float4 *)&g_wct[((size_t)k2 * HH + i0 + br_) * HH + o0 + bo];
            }
        }
        #pragma unroll
        for (int kq = 0; kq < 8; kq++) {
            float4 a4[8];
            #pragma unroll
            for (int rr = 0; rr < 8; rr++)
                a4[rr] = *(const float4 *)&As[ty * 8 + rr][kq * 4];
            int kk = kq * 4;
            CONV_FFMA(x) CONV_FFMA(y) CONV_FFMA(z) CONV_FFMA(w)
        }
    }
    #pragma unroll
    for (int rr = 0; rr < 8; rr++) {
        int b = ty * 8 + rr;
        #pragma unroll
        for (int c = 0; c < 4; c++) {
            float2 v = up2(acc[rr][c]);
            #pragma unroll
            for (int l = 0; l < 2; l++) {
                int o = o0 + (c >> 1) * 64 + tx * 4 + (c & 1) * 2 + l;
                float cv = (l ? v.y : v.x) + bc[o];
                out[((size_t)b * TT + t) * HH + o] =
                    g_theme[((size_t)t * BB + b) * HH + o] * cv +
                    g_h[((size_t)t * BB + b) * HH + o];
            }
        }
    }
}

extern "C" void kernel_launch(void* const* d_in, const int* in_sizes, int n_in,
                              void* d_out, int out_size) {
    const float *x   = (const float *)d_in[0];
    const float *Wk  = (const float *)d_in[2];
    const float *bk  = (const float *)d_in[3];
    const float *Wr  = (const float *)d_in[4];
    const float *br  = (const float *)d_in[5];
    const float *Ws  = (const float *)d_in[6];
    const float *bs  = (const float *)d_in[7];
    const float *Wrs = (const float *)d_in[8];
    const float *brs = (const float *)d_in[9];
    const float *Wc  = (const float *)d_in[10];
    const float *bc  = (const float *)d_in[11];
    float *out = (float *)d_out;

    const int p1_smem = (KH * 64 + KH * 8 + KH * APAD + 4 * 192 + 96 + 96) * 4;
    cudaFuncSetAttribute(phase1_main,
                         cudaFuncAttributeMaxDynamicSharedMemorySize, p1_smem);
    const int th_smem = (384 * 64 + 64 * 384 + 16 * 384 + 16 * 64 + 160) * 4;  // 225,920
    cudaFuncSetAttribute(theme_kernel,
                         cudaFuncAttributeMaxDynamicSharedMemorySize, th_smem);

    xk_kernel<<<dim3(512, 13), 256>>>(x, Wk, bk, Wr, br);
    wct_kernel<<<(CK * HH * HH + 255) / 256, 256>>>(Wc);
    phase1_main<<<NBLK, 512, p1_smem>>>(Wr);
    theme_kernel<<<148, 256, th_smem>>>(Ws, bs, Wrs, brs);
    conv_kernel<<<dim3(TT, 3), 256>>>(bc, out);
}

// round 16
// speedup vs baseline: 1.2628x; 1.2110x over previous
#include <cuda_runtime.h>
#include <cstdint>
#include <math.h>

#define BB 128
#define TT 512
#define DD 128
#define HH 384
#define GG 1542
#define GPAD 1664
#define HSS 64
#define CK 10
#define GT 24
#define NBLK (GT * 4)
#define KH 384
#define APAD 40

__device__ float g_h[(size_t)TT * BB * HH];
__device__ float g_dist[TT * BB];
__device__ float g_theme[(size_t)TT * BB * HH];
__device__ float g_wct[CK * HH * HH];
__device__ float g_xk[(size_t)TT * BB * GPAD];
__device__ unsigned g_cnt2[4];
__device__ unsigned g_gen2[4];
__device__ unsigned g_task;
__device__ unsigned g_thdone[TT];

typedef unsigned long long u64;
__device__ __forceinline__ u64 pk2(float a, float b) {
    u64 r; asm("mov.b64 %0,{%1,%2};" : "=l"(r) : "f"(a), "f"(b)); return r;
}
__device__ __forceinline__ void fma2(u64 &d, u64 a, u64 b) {
    asm("fma.rn.f32x2 %0,%1,%2,%0;" : "+l"(d) : "l"(a), "l"(b));
}
__device__ __forceinline__ float2 up2(u64 v) {
    float2 r; asm("mov.b64 {%0,%1},%2;" : "=f"(r.x), "=f"(r.y) : "l"(v)); return r;
}
__device__ __forceinline__ float ftanh(float x) {
    float y; asm("tanh.approx.f32 %0,%1;" : "=f"(y) : "f"(x)); return y;
}
__device__ __forceinline__ float sgm(float x) { return 0.5f * ftanh(0.5f * x) + 0.5f; }

__device__ __forceinline__ void group_bar(int grp) {
    __syncthreads();
    if (threadIdx.x == 0) {
        unsigned *gp = &g_gen2[grp];
        unsigned old;
        asm volatile("ld.global.u32 %0, [%1];" : "=r"(old) : "l"(gp) : "memory");
        unsigned prev;
        asm volatile("atom.add.acq_rel.gpu.global.u32 %0, [%1], 1;"
                     : "=r"(prev) : "l"(&g_cnt2[grp]) : "memory");
        if (prev == GT - 1) {
            g_cnt2[grp] = 0;
            asm volatile("st.release.gpu.global.u32 [%0], %1;"
                         :: "l"(gp), "r"(old + 1) : "memory");
        } else {
            unsigned v;
            do {
                asm volatile("ld.acquire.gpu.global.u32 %0, [%1];"
                             : "=r"(v) : "l"(gp) : "memory");
            } while (v == old);
        }
    }
    __syncthreads();
}

__device__ __forceinline__ void calc_dis(int t, int b, float *dis) {
    float cs = 0.f, c[CK];
    #pragma unroll
    for (int k = 0; k < CK; k++) {
        int s = t - (CK - 1) + k;
        cs += (s >= 0) ? g_dist[s * BB + b] : 0.f;
        c[k] = cs;
    }
    float mx = c[0];
    #pragma unroll
    for (int k = 1; k < CK; k++) mx = fmaxf(mx, c[k]);
    float sum = 0.f;
    #pragma unroll
    for (int k = 0; k < CK; k++) { c[k] = __expf(c[k] - mx); sum += c[k]; }
    float is = 1.f / sum;
    #pragma unroll
    for (int k = 0; k < CK; k++) dis[k] = c[k] * is;
}

__device__ __forceinline__ void wait_gen_ge(int t) {
    #pragma unroll
    for (int g = 0; g < 4; g++) {
        unsigned v;
        do {
            asm volatile("ld.acquire.gpu.global.u32 %0, [%1];"
                         : "=r"(v) : "l"(&g_gen2[g]) : "memory");
        } while (v < (unsigned)(t + 1));
    }
}
__device__ __forceinline__ void wait_theme(int t) {
    unsigned v;
    do {
        asm volatile("ld.acquire.gpu.global.u32 %0, [%1];"
                     : "=r"(v) : "l"(&g_thdone[t]) : "memory");
    } while (v < 8u);
}

__global__ void init_kernel() {
    int i = blockIdx.x * 256 + threadIdx.x;
    if (i < TT) g_thdone[i] = 0;
    if (i < 4) { g_gen2[i] = 0; g_cnt2[i] = 0; }
    if (i == 0) g_task = 0;
}

__global__ void wct_kernel(const float * __restrict__ Wc) {
    int e = blockIdx.x * 256 + threadIdx.x;
    if (e < CK * HH * HH) {
        int o = e % HH, i = (e / HH) % HH, k = e / (HH * HH);
        g_wct[e] = Wc[((size_t)o * HH + i) * CK + k];
    }
}

// ---------- XK precompute (proven) ----------
#define XK_FFMA(COMP)                                                       \
    {                                                                       \
        ulonglong2 b0v = *(const ulonglong2 *)&Bs[kk][tx * 4];              \
        ulonglong2 b1v = *(const ulonglong2 *)&Bs[kk][tx * 4 + 64];         \
        _Pragma("unroll")                                                   \
        for (int rr = 0; rr < 8; rr++) {                                    \
            float av = a4[rr].COMP;                                         \
            u64 aa = pk2(av, av);                                           \
            fma2(acc[rr][0], aa, b0v.x); fma2(acc[rr][1], aa, b0v.y);       \
            fma2(acc[rr][2], aa, b1v.x); fma2(acc[rr][3], aa, b1v.y);       \
        }                                                                   \
        kk++;                                                               \
    }

__global__ __launch_bounds__(256) void xk_kernel(
    const float * __restrict__ x, const float * __restrict__ Wk,
    const float * __restrict__ bk, const float * __restrict__ Wr,
    const float * __restrict__ br)
{
    int b = blockIdx.x >> 2, t0 = (blockIdx.x & 3) * 128;
    int g0 = blockIdx.y * 128;
    int tid = threadIdx.x, tx = tid & 15, ty = tid >> 4;
    __shared__ __align__(16) float As[128][20];
    __shared__ __align__(16) float Bs[16][128];

    u64 acc[8][4];
    #pragma unroll
    for (int a = 0; a < 8; a++)
        #pragma unroll
        for (int c = 0; c < 4; c++) acc[a][c] = 0ull;

    for (int ch = 0; ch < 8; ch++) {
        int k0 = ch * 16;
        __syncthreads();
        #pragma unroll
        for (int l = 0; l < 8; l++) {
            int e = tid + l * 256;
            As[e >> 4][e & 15] = x[((size_t)b * TT + t0 + (e >> 4)) * DD + k0 + (e & 15)];
            int g = g0 + (e & 127);
            Bs[e >> 7][e & 127] = (g < GG) ? Wk[(size_t)(k0 + (e >> 7)) * GG + g] : 0.f;
        }
        __syncthreads();
        #pragma unroll
        for (int kq = 0; kq < 4; kq++) {
            float4 a4[8];
            #pragma unroll
            for (int rr = 0; rr < 8; rr++)
                a4[rr] = *(const float4 *)&As[ty * 8 + rr][kq * 4];
            int kk = kq * 4;
            XK_FFMA(x) XK_FFMA(y) XK_FFMA(z) XK_FFMA(w)
        }
    }
    #pragma unroll
    for (int rr = 0; rr < 8; rr++) {
        int t = t0 + ty * 8 + rr;
        #pragma unroll
        for (int c = 0; c < 4; c++) {
            float2 v = up2(acc[rr][c]);
            #pragma unroll
            for (int l = 0; l < 2; l++) {
                int g = g0 + (c >> 1) * 64 + tx * 4 + (c & 1) * 2 + l;
                if (g < GG) {
                    float bias = bk[g] + br[g] + Wk[(size_t)DD * GG + g] + Wr[(size_t)HH * GG + g];
                    int gp = (g < 6) ? (1536 + g) : (g - 6);
                    g_xk[((size_t)t * BB + b) * GPAD + gp] = (l ? v.y : v.x) + bias;
                }
            }
        }
    }
}

// ---------- phase-1 body (R13 proven, as device fn) ----------
__device__ void phase1_body(const float * __restrict__ Wr, float *sm, int blk)
{
    float *Bs   = sm;
    float *Bsm  = Bs + KH * 64;
    float *As   = Bsm + KH * 8;
    float *Msum = As + KH * APAD;
    float *fms  = Msum + 4 * 192;
    float *ims  = fms + 96;

    int tid = threadIdx.x;
    int gt = blk % GT, bt = blk / GT;
    int b0 = bt * 32;

    for (int j = 0; j < (KH * 64) / 512; j++) {
        int e = tid + j * 512;
        int gg = e & 63, k = e >> 6, q = gg >> 4, m = gg & 15;
        Bs[e] = Wr[(size_t)k * GG + 6 + 384 * q + 16 * gt + m];
    }
    for (int e = tid; e < KH * 8; e += 512) {
        int g = e & 7, k = e >> 3;
        Bsm[e] = (g < 6) ? Wr[(size_t)k * GG + g] : 0.f;
    }
    __syncthreads();

    int kc = tid >> 7, r = tid & 127;
    int tx = r & 15, ty = r >> 4;
    int sb = tid >> 4, sj = tid & 15;
    int ub = tid >> 4, um = tid & 15;
    int ui = gt * 16 + um, ul = ui >> 7;
    float creg = 0.f;
    int mid0 = 2 * r, mb = mid0 / 6, mg0 = mid0 % 6;

    for (int t = 0; t < TT; t++) {
        float4 xkp[4];
        if (kc == 0) {
            int gp = 384 * (tx >> 2) + 16 * gt + (tx & 3) * 4;
            #pragma unroll
            for (int a = 0; a < 4; a++)
                xkp[a] = *(const float4 *)&g_xk[((size_t)t * BB + b0 + ty * 4 + a) * GPAD + gp];
        }
        float xkm[6];
        if (tid >= 128 && tid < 160) {
            int b = tid - 128;
            float4 v4 = *(const float4 *)&g_xk[((size_t)t * BB + b0 + b) * GPAD + 1536];
            float2 v2 = *(const float2 *)&g_xk[((size_t)t * BB + b0 + b) * GPAD + 1540];
            xkm[0] = v4.x; xkm[1] = v4.y; xkm[2] = v4.z; xkm[3] = v4.w;
            xkm[4] = v2.x; xkm[5] = v2.y;
        }

        #pragma unroll
        for (int j = 0; j < 6; j++) {
            int k4 = (sj + j * 16) * 4;
            float4 v;
            if (t > 0) v = *(const float4 *)&g_h[((size_t)(t - 1) * BB + b0 + sb) * HH + k4];
            else { v.x = v.y = v.z = v.w = 0.f; }
            As[(k4 + 0) * APAD + sb] = v.x;
            As[(k4 + 1) * APAD + sb] = v.y;
            As[(k4 + 2) * APAD + sb] = v.z;
            As[(k4 + 3) * APAD + sb] = v.w;
        }
        __syncthreads();

        u64 acc[4][2];
        #pragma unroll
        for (int a = 0; a < 4; a++) { acc[a][0] = 0ull; acc[a][1] = 0ull; }
        int kbeg = kc * (KH / 4);
        #pragma unroll 6
        for (int kk = kbeg; kk < kbeg + KH / 4; kk++) {
            float4 av = *(const float4 *)&As[kk * APAD + ty * 4];
            ulonglong2 bv = *(const ulonglong2 *)&Bs[kk * 64 + tx * 4];
            u64 aa;
            aa = pk2(av.x, av.x); fma2(acc[0][0], aa, bv.x); fma2(acc[0][1], aa, bv.y);
            aa = pk2(av.y, av.y); fma2(acc[1][0], aa, bv.x); fma2(acc[1][1], aa, bv.y);
            aa = pk2(av.z, av.z); fma2(acc[2][0], aa, bv.x); fma2(acc[2][1], aa, bv.y);
            aa = pk2(av.w, av.w); fma2(acc[3][0], aa, bv.x); fma2(acc[3][1], aa, bv.y);
        }
        float mp0 = 0.f, mp1 = 0.f;
        if (r < 96) {
            for (int kk = kbeg; kk < kbeg + KH / 4; kk++) {
                float a = As[kk * APAD + mb];
                mp0 += a * Bsm[kk * 8 + mg0];
                mp1 += a * Bsm[kk * 8 + mg0 + 1];
            }
        }
        __syncthreads();

        ulonglong2 *red = (ulonglong2 *)As;
        float *res = (float *)(red + 3 * 512);
        if (kc) {
            #pragma unroll
            for (int a = 0; a < 4; a++) {
                ulonglong2 v; v.x = acc[a][0]; v.y = acc[a][1];
                red[(size_t)(kc - 1) * 512 + a * 128 + r] = v;
            }
        }
        if (r < 96) *(float2 *)&Msum[kc * 192 + mid0] = make_float2(mp0, mp1);
        __syncthreads();

        if (kc == 0) {
            #pragma unroll
            for (int a = 0; a < 4; a++) {
                float2 s0 = up2(acc[a][0]), s1 = up2(acc[a][1]);
                #pragma unroll
                for (int q = 0; q < 3; q++) {
                    ulonglong2 v = red[(size_t)q * 512 + a * 128 + r];
                    float2 o0 = up2(v.x), o1 = up2(v.y);
                    s0.x += o0.x; s0.y += o0.y; s1.x += o1.x; s1.y += o1.y;
                }
                float4 w;
                w.x = s0.x + xkp[a].x; w.y = s0.y + xkp[a].y;
                w.z = s1.x + xkp[a].z; w.w = s1.y + xkp[a].w;
                *(float4 *)&res[(ty * 4 + a) * 64 + tx * 4] = w;
            }
        }
        if (tid >= 128 && tid < 160) {
            int b = tid - 128;
            float pre[6];
            #pragma unroll
            for (int g = 0; g < 6; g++)
                pre[g] = Msum[b * 6 + g] + Msum[192 + b * 6 + g]
                       + Msum[384 + b * 6 + g] + Msum[576 + b * 6 + g] + xkm[g];
            float m = fmaxf(pre[0], fmaxf(pre[1], pre[2]));
            float e0 = __expf(pre[0] - m), e1 = __expf(pre[1] - m), e2 = __expf(pre[2] - m);
            float inv = 1.f / (e0 + e1 + e2);
            float f0 = e0 * inv, f1 = f0 + e1 * inv, f2 = f1 + e2 * inv;
            fms[b * 3 + 0] = f0; fms[b * 3 + 1] = f1; fms[b * 3 + 2] = f2;
            float mi = fmaxf(pre[3], fmaxf(pre[4], pre[5]));
            float q0 = __expf(pre[3] - mi), q1 = __expf(pre[4] - mi), q2 = __expf(pre[5] - mi);
            float iv = 1.f / (q0 + q1 + q2);
            float i2 = q2 * iv, i1 = i2 + q1 * iv, i0 = i1 + q0 * iv;
            ims[b * 3 + 0] = i0; ims[b * 3 + 1] = i1; ims[b * 3 + 2] = i2;
            if (gt == 0) g_dist[t * BB + b0 + b] = 1.f - (f0 + f1 + f2) * (1.f / 3.f);
        }
        __syncthreads();

        {
            float fgv = sgm(res[ub * 64 + um]);
            float igv = sgm(res[ub * 64 + 16 + um]);
            float ogv = sgm(res[ub * 64 + 32 + um]);
            float civ = ftanh(res[ub * 64 + 48 + um]);
            float fm = fms[ub * 3 + ul], im = ims[ub * 3 + ul];
            float ov = fm * im;
            creg = creg * (ov * fgv + fm - ov) + civ * (ov * igv + im - ov);
            g_h[((size_t)t * BB + b0 + ub) * HH + ui] = ogv * ftanh(creg);
        }
        group_bar(bt);
    }
}

// ---------- theme tile (R10 numerics, 512 threads, 16 b) ----------
__device__ void theme_tile(float *dsm, int t, int b0,
    const float * __restrict__ Ws, const float * __restrict__ bs,
    const float * __restrict__ Wrs, const float * __restrict__ brs)
{
    float (*diss)[CK] = (float (*)[CK])dsm;        // [16][10]
    float *wm = dsm + 160;                         // [16][384]
    float *s1 = dsm + 160 + 16 * HH;               // [16][64]
    int tid = threadIdx.x;
    if (tid < 16) calc_dis(t, b0 + tid, diss[tid]);
    __syncthreads();
    #pragma unroll
    for (int j = 0; j < 12; j++) {
        int e = tid + j * 512, b = e / HH, i = e % HH;
        float a = 0.f;
        #pragma unroll
        for (int k = 0; k < CK; k++) {
            int s = t - (CK - 1) + k;
            if (s >= 0) a += diss[b][k] * g_h[((size_t)s * BB + b0 + b) * HH + i];
        }
        wm[b * HH + i] = a * (1.f / CK);
    }
    __syncthreads();
    #pragma unroll
    for (int j = 0; j < 2; j++) {
        int e = tid + j * 512, b = e >> 6, hs = e & 63;
        float a = 0.f;
        for (int i = 0; i < HH; i++) a += wm[b * HH + i] * Ws[i * HSS + hs];
        s1[b * 64 + hs] = fmaxf(a + bs[hs], 0.f);
    }
    __syncthreads();
    #pragma unroll
    for (int j = 0; j < 12; j++) {
        int e = tid + j * 512, b = e / HH, o = e % HH;
        float a = 0.f;
        #pragma unroll
        for (int hs = 0; hs < HSS; hs++) a += s1[b * 64 + hs] * Wrs[hs * HH + o];
        g_theme[((size_t)t * BB + b0 + b) * HH + o] = sgm(a + brs[o]);
    }
}

// ---------- conv block (R12 512-thread version, proven pass) ----------
#define CONV_FFMA(COMP)                                                     \
    {                                                                       \
        ulonglong2 bv = *(const ulonglong2 *)&Bs[kk][tx * 4];               \
        _Pragma("unroll")                                                   \
        for (int rr = 0; rr < 8; rr++) {                                    \
            float av = a4[rr].COMP;                                         \
            u64 aa = pk2(av, av);                                           \
            fma2(acc[rr][0], aa, bv.x); fma2(acc[rr][1], aa, bv.y);         \
        }                                                                   \
        kk++;                                                               \
    }

__device__ void conv_block(float *dsm, int t, int o0,
                           const float * __restrict__ bc, float * __restrict__ out)
{
    float (*dis_s)[CK] = (float (*)[CK])dsm;             // [128][10]
    float (*As)[36] = (float (*)[36])(dsm + 1280);       // [128][36]
    float (*Bs)[128] = (float (*)[128])(dsm + 1280 + 128 * 36);  // [32][128]
    int tid = threadIdx.x;
    int tx = tid & 31, ty = tid >> 5;
    if (tid < BB) calc_dis(t, tid, dis_s[tid]);
    __syncthreads();

    u64 acc[8][2];
    #pragma unroll
    for (int a = 0; a < 8; a++) { acc[a][0] = 0ull; acc[a][1] = 0ull; }

    const int NCH = CK * (HH / 32);
    float4 pa[2], pb[2];
    {
        int s = t - (CK - 1);
        #pragma unroll
        for (int l = 0; l < 2; l++) {
            int f = tid + l * 512;
            int ab = f >> 3, ai = (f & 7) * 4;
            pa[l].x = pa[l].y = pa[l].z = pa[l].w = 0.f;
            if (s >= 0) pa[l] = *(const float4 *)&g_h[((size_t)s * BB + ab) * HH + ai];
            int br_ = f >> 5, bo = (f & 31) * 4;
            pb[l] = *(const float4 *)&g_wct[(size_t)br_ * HH + o0 + bo];
        }
    }
    for (int ch = 0; ch < NCH; ch++) {
        int k = ch / 12;
        __syncthreads();
        #pragma unroll
        for (int l = 0; l < 2; l++) {
            int f = tid + l * 512;
            int ab = f >> 3, ai = (f & 7) * 4;
            float d = dis_s[ab][k];
            float4 v = pa[l];
            v.x *= d; v.y *= d; v.z *= d; v.w *= d;
            *(float4 *)&As[ab][ai] = v;
            int br_ = f >> 5, bo = (f & 31) * 4;
            *(float4 *)&Bs[br_][bo] = pb[l];
        }
        __syncthreads();
        if (ch + 1 < NCH) {
            int k2 = (ch + 1) / 12, i0 = ((ch + 1) % 12) * 32, s = t - (CK - 1) + k2;
            #pragma unroll
            for (int l = 0; l < 2; l++) {
                int f = tid + l * 512;
                int ab = f >> 3, ai = (f & 7) * 4;
                pa[l].x = pa[l].y = pa[l].z = pa[l].w = 0.f;
                if (s >= 0) pa[l] = *(const float4 *)&g_h[((size_t)s * BB + ab) * HH + i0 + ai];
                int br_ = f >> 5, bo = (f & 31) * 4;
                pb[l] = *(const float4 *)&g_wct[((size_t)k2 * HH + i0 + br_) * HH + o0 + bo];
            }
        }
        #pragma unroll
        for (int kq = 0; kq < 8; kq++) {
            float4 a4[8];
            #pragma unroll
            for (int rr = 0; rr < 8; rr++)
                a4[rr] = *(const float4 *)&As[ty * 8 + rr][kq * 4];
            int kk = kq * 4;
            CONV_FFMA(x) CONV_FFMA(y) CONV_FFMA(z) CONV_FFMA(w)
        }
    }
    float4 bc4 = *(const float4 *)&bc[o0 + tx * 4];
    #pragma unroll
    for (int rr = 0; rr < 8; rr++) {
        int b = ty * 8 + rr;
        float2 v0 = up2(acc[rr][0]), v1 = up2(acc[rr][1]);
        float4 th = *(const float4 *)&g_theme[((size_t)t * BB + b) * HH + o0 + tx * 4];
        float4 hh = *(const float4 *)&g_h[((size_t)t * BB + b) * HH + o0 + tx * 4];
        float4 w;
        w.x = th.x * (v0.x + bc4.x) + hh.x;
        w.y = th.y * (v0.y + bc4.y) + hh.y;
        w.z = th.z * (v1.x + bc4.z) + hh.z;
        w.w = th.w * (v1.y + bc4.w) + hh.w;
        *(float4 *)&out[((size_t)b * TT + t) * HH + o0 + tx * 4] = w;
    }
}

// ---------- mega: phase1 (blocks 0..95) + overlapped workers ----------
__global__ __launch_bounds__(512, 1) void mega_kernel(
    const float * __restrict__ Wr,
    const float * __restrict__ Ws, const float * __restrict__ bs,
    const float * __restrict__ Wrs, const float * __restrict__ brs,
    const float * __restrict__ bc, float * __restrict__ out)
{
    extern __shared__ float dsm[];
    __shared__ unsigned s_task;

    if (blockIdx.x < NBLK) phase1_body(Wr, dsm, blockIdx.x);
    __syncthreads();

    const unsigned NTASK = TT * 11;   // per t: 8 theme tiles then 3 conv o-tiles
    for (;;) {
        if (threadIdx.x == 0) s_task = atomicAdd(&g_task, 1u);
        __syncthreads();
        unsigned task = s_task;
        if (task >= NTASK) break;
        int t = task / 11, r = task % 11;
        if (threadIdx.x == 0) {
            wait_gen_ge(t);
            if (r >= 8) wait_theme(t);
        }
        __syncthreads();
        if (r < 8) {
            theme_tile(dsm, t, r * 16, Ws, bs, Wrs, brs);
            __syncthreads();
            if (threadIdx.x == 0)
                asm volatile("red.add.release.gpu.global.u32 [%0], %1;"
                             :: "l"(&g_thdone[t]), "r"(1u) : "memory");
        } else {
            conv_block(dsm, t, (r - 8) * 128, bc, out);
        }
        __syncthreads();
    }
}

extern "C" void kernel_launch(void* const* d_in, const int* in_sizes, int n_in,
                              void* d_out, int out_size) {
    const float *x   = (const float *)d_in[0];
    const float *Wk  = (const float *)d_in[2];
    const float *bk  = (const float *)d_in[3];
    const float *Wr  = (const float *)d_in[4];
    const float *br  = (const float *)d_in[5];
    const float *Ws  = (const float *)d_in[6];
    const float *bs  = (const float *)d_in[7];
    const float *Wrs = (const float *)d_in[8];
    const float *brs = (const float *)d_in[9];
    const float *Wc  = (const float *)d_in[10];
    const float *bc  = (const float *)d_in[11];
    float *out = (float *)d_out;

    const int mg_smem = (KH * 64 + KH * 8 + KH * APAD + 4 * 192 + 96 + 96) * 4; // 175872
    cudaFuncSetAttribute(mega_kernel, cudaFuncAttributeMaxDynamicSharedMemorySize, mg_smem);

    init_kernel<<<2, 256>>>();
    wct_kernel<<<(CK * HH * HH + 255) / 256, 256>>>(Wc);
    xk_kernel<<<dim3(512, 13), 256>>>(x, Wk, bk, Wr, br);
    mega_kernel<<<148, 512, mg_smem>>>(Wr, Ws, bs, Wrs, brs, bc, out);
}